// round 12
// baseline (speedup 1.0000x reference)
#include <cuda_runtime.h>
#include <math.h>

// HamiltonianFlow: dq/dt = p, dp/dt = -(q + q^3) — Duffing oscillator, exact.
//   E = p^2/2 + q^2/2 + q^4/4,  A^2 = 4E/(1+sqrt(1+4E)),  omega = sqrt(1+A^2),
//   m = k^2 = A^2/(2(1+A^2)) < 1/2,  q(t) = A cn(u0 + omega t, k).
// Initial Jacobi triple read directly from (q0,p0); shift b = 10*omega via
// 3-level descending Landen cascade (trig bottom, Cody-Waite 2pi reduction),
// combined with the Jacobi addition theorem. All roots via MUFU.RSQ
// (x*rsqrt(x)) to avoid non-fast-math sqrtf slow paths.
// One pair per thread (R11 showed warps beat intra-thread ILP here).

__device__ __forceinline__ float fsq(float x) {   // sqrt for x > 0
    return x * __frsqrt_rn(x);
}

__global__ __launch_bounds__(256) void ham_exact_kernel(
    const float2* __restrict__ in, float2* __restrict__ out, int n)
{
    int i = blockIdx.x * blockDim.x + threadIdx.x;
    if (i >= n) return;

    float2 qp = in[i];
    float q0 = qp.x, p0 = qp.y;

    // ---- energy, amplitude, frequency, modulus ----
    float q2 = q0 * q0;
    float E  = fmaf(0.5f * p0, p0, fmaf(0.25f * q2, q2, 0.5f * q2));
    float r1 = fsq(fmaf(4.0f, E, 1.0f));             // sqrt(1+4E) >= 1
    float A2 = fmaxf(__fdividef(4.0f * E, 1.0f + r1), 1e-12f);
    float w2 = 1.0f + A2;
    float omega = fsq(w2);
    float m  = __fdividef(A2, 2.0f * w2);            // k^2 in (0, 0.5)

    // ---- initial Jacobi triple from (q0, p0) ----
    float invA = __frsqrt_rn(A2);
    float A    = A2 * invA;
    float cn0  = fminf(fmaxf(q0 * invA, -1.0f), 1.0f);
    float sn0sq = fmaxf(fmaf(-cn0, cn0, 1.0f), 1e-20f);
    float dn0  = fsq(fmaf(-m, sn0sq, 1.0f));         // >= sqrt(1-m) > 0.7
    float sn0  = copysignf(fsq(sn0sq), -p0);         // p = -A w sn dn

    // ---- descending Landen cascade: k -> k1 -> k2 -> k3 ----
    float kp  = fsq(1.0f - m);                       // >= 0.707
    float k1  = __fdividef(1.0f - kp,  1.0f + kp);   // <= 0.172
    float kp1 = fsq(fmaf(-k1, k1, 1.0f));
    float k2  = __fdividef(1.0f - kp1, 1.0f + kp1);  // <= 7.4e-3
    float kp2 = fsq(fmaf(-k2, k2, 1.0f));
    float k3  = __fdividef(1.0f - kp2, 1.0f + kp2);  // <= 1.4e-5
    float Pfac = (1.0f + k1) * (1.0f + k2) * (1.0f + k3);

    // ---- forward evaluation at b = 10*omega ----
    float v = __fdividef(10.0f * omega, Pfac);       // <= ~50
    const float INV2PI = 0.15915494309189535f;
    const float PI2_HI = 6.28125f;                   // exact in fp32
    const float PI2_LO = 1.9353071795864769e-3f;
    float nn = rintf(v * INV2PI);
    float r  = fmaf(-nn, PI2_HI, v);
    r = fmaf(-nn, PI2_LO, r);
    float sn = __sinf(r), cn = __cosf(r), dn = 1.0f;

    #define HAM_ASCEND(kk) {                                   \
        float ks2  = (kk) * sn * sn;                           \
        float rden = __frcp_rn(1.0f + ks2);                    \
        float snn  = (1.0f + (kk)) * sn * rden;                \
        float cnn  = cn * dn * rden;                           \
        dn = (1.0f - ks2) * rden; sn = snn; cn = cnn; }
    HAM_ASCEND(k3)
    HAM_ASCEND(k2)
    HAM_ASCEND(k1)
    #undef HAM_ASCEND

    // ---- addition theorem: u = u0 + b ----
    float D   = __frcp_rn(fmaf(-m * sn0sq, sn * sn, 1.0f));
    float snu = (sn0 * cn * dn + sn * cn0 * dn0) * D;
    float cnu = fmaf(cn0, cn, -(sn0 * dn0) * (sn * dn)) * D;
    float dnu = fmaf(dn0, dn, -(m * sn0 * sn) * (cn0 * cn)) * D;

    out[i] = make_float2(A * cnu, -A * omega * snu * dnu);
}

extern "C" void kernel_launch(void* const* d_in, const int* in_sizes, int n_in,
                              void* d_out, int out_size) {
    const float2* in = (const float2*)d_in[0];
    float2* out = (float2*)d_out;
    int n = in_sizes[0] / 2;               // 262144 (q,p) pairs
    int block = 256;
    int grid = (n + block - 1) / block;    // 1024 blocks over 148 SMs
    ham_exact_kernel<<<grid, block>>>(in, out, n);
}

// round 13
// speedup vs baseline: 1.1535x; 1.1535x over previous
#include <cuda_runtime.h>
#include <math.h>

// HamiltonianFlow: dq/dt = p, dp/dt = -(q + q^3) — Duffing oscillator, exact.
//   E = p^2/2 + q^2/2 + q^4/4,  A^2 = 4E/(1+sqrt(1+4E)),  omega = sqrt(1+A^2),
//   m = k^2 = A^2/(2(1+A^2)) < 1/2,  q(t) = A cn(u0 + omega t, k).
// Initial Jacobi triple read directly from (q0,p0); shift b = 10*omega via
// 3-level descending Landen cascade (trig bottom, Cody-Waite 2pi reduction),
// combined with the Jacobi addition theorem.
// All roots/reciprocals are single-MUFU .approx ops (NOT the *_rn IEEE
// intrinsics, which expand to Newton fixup sequences — measured regression).

__device__ __forceinline__ float fsqrt_ap(float x) {
    float r; asm("sqrt.approx.f32 %0, %1;" : "=f"(r) : "f"(x)); return r;
}
__device__ __forceinline__ float frcp_ap(float x) {
    float r; asm("rcp.approx.f32 %0, %1;" : "=f"(r) : "f"(x)); return r;
}
__device__ __forceinline__ float frsqrt_ap(float x) {
    float r; asm("rsqrt.approx.f32 %0, %1;" : "=f"(r) : "f"(x)); return r;
}

__global__ __launch_bounds__(256) void ham_exact_kernel(
    const float2* __restrict__ in, float2* __restrict__ out, int n)
{
    int i = blockIdx.x * blockDim.x + threadIdx.x;
    if (i >= n) return;

    float2 qp = in[i];
    float q0 = qp.x, p0 = qp.y;

    // ---- energy, amplitude, frequency, modulus ----
    float q2 = q0 * q0;
    float E  = fmaf(0.5f * p0, p0, fmaf(0.25f * q2, q2, 0.5f * q2));
    float r1 = fsqrt_ap(fmaf(4.0f, E, 1.0f));        // sqrt(1+4E) >= 1
    float A2 = fmaxf(4.0f * E * frcp_ap(1.0f + r1), 1e-12f);
    float w2 = 1.0f + A2;
    float omega = fsqrt_ap(w2);
    float m  = A2 * frcp_ap(2.0f * w2);              // k^2 in (0, 0.5)

    // ---- initial Jacobi triple from (q0, p0) ----
    float invA = frsqrt_ap(A2);
    float A    = A2 * invA;
    float cn0  = fminf(fmaxf(q0 * invA, -1.0f), 1.0f);
    float sn0sq = fmaxf(fmaf(-cn0, cn0, 1.0f), 0.0f);
    float dn0  = fsqrt_ap(fmaf(-m, sn0sq, 1.0f));    // >= sqrt(1-m) > 0.7
    float sn0  = copysignf(fsqrt_ap(sn0sq), -p0);    // p = -A w sn dn

    // ---- descending Landen cascade: k -> k1 -> k2 -> k3 ----
    float kp  = fsqrt_ap(1.0f - m);                  // >= 0.707
    float k1  = (1.0f - kp)  * frcp_ap(1.0f + kp);   // <= 0.172
    float kp1 = fsqrt_ap(fmaf(-k1, k1, 1.0f));
    float k2  = (1.0f - kp1) * frcp_ap(1.0f + kp1);  // <= 7.4e-3
    float kp2 = fsqrt_ap(fmaf(-k2, k2, 1.0f));
    float k3  = (1.0f - kp2) * frcp_ap(1.0f + kp2);  // <= 1.4e-5
    float Pfac = (1.0f + k1) * (1.0f + k2) * (1.0f + k3);

    // ---- forward evaluation at b = 10*omega ----
    float v = 10.0f * omega * frcp_ap(Pfac);         // <= ~50
    const float INV2PI = 0.15915494309189535f;
    const float PI2_HI = 6.28125f;                   // exact in fp32
    const float PI2_LO = 1.9353071795864769e-3f;
    float nn = rintf(v * INV2PI);
    float r  = fmaf(-nn, PI2_HI, v);
    r = fmaf(-nn, PI2_LO, r);
    float sn = __sinf(r), cn = __cosf(r), dn = 1.0f;

    #define HAM_ASCEND(kk) {                                   \
        float ks2  = (kk) * sn * sn;                           \
        float rden = frcp_ap(1.0f + ks2);                      \
        float snn  = (1.0f + (kk)) * sn * rden;                \
        float cnn  = cn * dn * rden;                           \
        dn = (1.0f - ks2) * rden; sn = snn; cn = cnn; }
    HAM_ASCEND(k3)
    HAM_ASCEND(k2)
    HAM_ASCEND(k1)
    #undef HAM_ASCEND

    // ---- addition theorem: u = u0 + b ----
    float D   = frcp_ap(fmaf(-m * sn0sq, sn * sn, 1.0f));
    float snu = (sn0 * cn * dn + sn * cn0 * dn0) * D;
    float cnu = fmaf(cn0, cn, -(sn0 * dn0) * (sn * dn)) * D;
    float dnu = fmaf(dn0, dn, -(m * sn0 * sn) * (cn0 * cn)) * D;

    out[i] = make_float2(A * cnu, -A * omega * snu * dnu);
}

extern "C" void kernel_launch(void* const* d_in, const int* in_sizes, int n_in,
                              void* d_out, int out_size) {
    const float2* in = (const float2*)d_in[0];
    float2* out = (float2*)d_out;
    int n = in_sizes[0] / 2;               // 262144 (q,p) pairs
    int block = 256;
    int grid = (n + block - 1) / block;    // 1024 blocks over 148 SMs
    ham_exact_kernel<<<grid, block>>>(in, out, n);
}

// round 14
// speedup vs baseline: 1.2930x; 1.1209x over previous
#include <cuda_runtime.h>
#include <math.h>

// HamiltonianFlow: dq/dt = p, dp/dt = -(q + q^3) — Duffing oscillator, exact.
//   E = p^2/2 + q^2/2 + q^4/4,  r1 = sqrt(1+4E),  A^2 = r1 - 1 (exact),
//   w^2 = 1+A^2 = r1,  omega = sqrt(r1),  m = k^2 = (1 - 1/r1)/2 < 1/2,
//   q(t) = A cn(u0 + omega t, k),  p(t) = -A omega sn dn.
// Initial Jacobi triple read directly from (q0,p0). Shift b = 10*omega via
// descending Landen: k->k1 (exact), k2,k3 by series; trig bottom (Cody-Waite
// 2pi reduction + __sinf/__cosf); two ascend levels (k3 level skipped,
// err <= k3 <= 1.4e-5); Jacobi addition theorem. All roots/recips are
// single-MUFU .approx ops; 12 MUFUs total, ~7 on the critical path.

__device__ __forceinline__ float fsqrt_ap(float x) {
    float r; asm("sqrt.approx.f32 %0, %1;" : "=f"(r) : "f"(x)); return r;
}
__device__ __forceinline__ float frcp_ap(float x) {
    float r; asm("rcp.approx.f32 %0, %1;" : "=f"(r) : "f"(x)); return r;
}
__device__ __forceinline__ float frsqrt_ap(float x) {
    float r; asm("rsqrt.approx.f32 %0, %1;" : "=f"(r) : "f"(x)); return r;
}

__global__ __launch_bounds__(256) void ham_exact_kernel(
    const float2* __restrict__ in, float2* __restrict__ out, int n)
{
    int i = blockIdx.x * blockDim.x + threadIdx.x;
    if (i >= n) return;

    float2 qp = in[i];
    float q0 = qp.x, p0 = qp.y;

    // ---- energy, amplitude, frequency, modulus ----
    float q2 = q0 * q0;
    float E  = fmaf(0.5f * p0, p0, fmaf(0.25f * q2, q2, 0.5f * q2));
    float r1 = fsqrt_ap(fmaf(4.0f, E, 1.0f));        // = 1 + A^2 = w^2
    float A2 = fmaxf(r1 - 1.0f, 1e-12f);             // exact identity
    float rsq = frsqrt_ap(r1);
    float omega  = r1 * rsq;                         // sqrt(r1)
    float m      = fmaf(-0.5f * rsq, rsq, 0.5f);     // (1 - 1/r1)/2 in (0,.5)

    // ---- initial Jacobi triple from (q0, p0) ----
    float invA = frsqrt_ap(A2);
    float A    = A2 * invA;
    float cn0  = fminf(fmaxf(q0 * invA, -1.0f), 1.0f);
    float sn0sq = fmaxf(fmaf(-cn0, cn0, 1.0f), 0.0f);
    float dn0  = fsqrt_ap(fmaf(-m, sn0sq, 1.0f));    // >= sqrt(1-m) > 0.7
    float sn0  = copysignf(fsqrt_ap(sn0sq), -p0);    // p = -A w sn dn

    // ---- Landen moduli: k1 exact, k2/k3 by series ----
    float kp  = fsqrt_ap(1.0f - m);                  // >= 0.707
    float k1  = (1.0f - kp) * frcp_ap(1.0f + kp);    // <= 0.172
    float t   = k1 * k1;                             // <= 0.0295
    float k2  = 0.25f * t * fmaf(t, fmaf(0.34375f, t, 0.5f), 1.0f); // <=7.4e-3
    float k3  = 0.25f * k2 * k2;                     // <= 1.4e-5
    float Pfac = (1.0f + k1) * (1.0f + (k2 + k3));   // 2K/pi

    // ---- forward evaluation at b = 10*omega ----
    float v = 10.0f * omega * frcp_ap(Pfac);         // <= ~50
    const float INV2PI = 0.15915494309189535f;
    const float PI2_HI = 6.28125f;                   // exact in fp32
    const float PI2_LO = 1.9353071795864769e-3f;
    float nn = rintf(v * INV2PI);
    float r  = fmaf(-nn, PI2_HI, v);
    r = fmaf(-nn, PI2_LO, r);
    float sn = __sinf(r), cn = __cosf(r);            // level-2 funcs (dn = 1)

    // ascend k2: 1/(1+x) ~= 1 - x + x^2  (x <= 7.4e-3, err 4e-7)
    float x2   = k2 * sn * sn;
    float rd2  = fmaf(x2, x2, 1.0f) - x2;
    float sn1  = (1.0f + k2) * sn * rd2;
    float cn1  = cn * rd2;
    float dn1  = (1.0f - x2) * rd2;

    // ascend k1: full reciprocal (x up to 0.172)
    float x1   = k1 * sn1 * sn1;
    float rd1  = frcp_ap(1.0f + x1);
    float snb  = (1.0f + k1) * sn1 * rd1;
    float cnb  = cn1 * dn1 * rd1;
    float dnb  = (1.0f - x1) * rd1;

    // ---- addition theorem: u = u0 + b ----
    float D   = frcp_ap(fmaf(-m * sn0sq, snb * snb, 1.0f));
    float snu = (sn0 * cnb * dnb + snb * cn0 * dn0) * D;
    float cnu = fmaf(cn0, cnb, -(sn0 * dn0) * (snb * dnb)) * D;
    float dnu = fmaf(dn0, dnb, -(m * sn0 * snb) * (cn0 * cnb)) * D;

    out[i] = make_float2(A * cnu, -A * omega * snu * dnu);
}

extern "C" void kernel_launch(void* const* d_in, const int* in_sizes, int n_in,
                              void* d_out, int out_size) {
    const float2* in = (const float2*)d_in[0];
    float2* out = (float2*)d_out;
    int n = in_sizes[0] / 2;               // 262144 (q,p) pairs
    int block = 256;
    int grid = (n + block - 1) / block;    // 1024 blocks over 148 SMs
    ham_exact_kernel<<<grid, block>>>(in, out, n);
}

// round 15
// speedup vs baseline: 1.3365x; 1.0337x over previous
#include <cuda_runtime.h>
#include <math.h>

// HamiltonianFlow: dq/dt = p, dp/dt = -(q + q^3) — Duffing oscillator, exact.
//   E = p^2/2 + q^2/2 + q^4/4,  r1 = sqrt(1+4E),  A^2 = r1 - 1 (exact),
//   w^2 = r1,  omega = sqrt(r1),  m = k^2 = (1 - 1/r1)/2 < 1/2,
//   q(t) = A cn(u0 + omega t, k),  p(t) = -A omega sn dn.
// Initial Jacobi triple direct from (q0,p0); shift b = 10*omega via Landen
// (k1 exact, k2/k3 series, trig bottom with Cody-Waite reduction, 2 ascend
// levels); Jacobi addition theorem. Single-MUFU .approx roots/recips.
// 2 pairs per thread: 4096 warps = ONE wave on 148 SMs (was 2 waves), with
// ILP-2 across the serial MUFU chain.

__device__ __forceinline__ float fsqrt_ap(float x) {
    float r; asm("sqrt.approx.f32 %0, %1;" : "=f"(r) : "f"(x)); return r;
}
__device__ __forceinline__ float frcp_ap(float x) {
    float r; asm("rcp.approx.f32 %0, %1;" : "=f"(r) : "f"(x)); return r;
}
__device__ __forceinline__ float frsqrt_ap(float x) {
    float r; asm("rsqrt.approx.f32 %0, %1;" : "=f"(r) : "f"(x)); return r;
}

__device__ __forceinline__ float2 duffing_exact(float q0, float p0) {
    // ---- energy, amplitude, frequency, modulus ----
    float q2 = q0 * q0;
    float E  = fmaf(0.5f * p0, p0, fmaf(0.25f * q2, q2, 0.5f * q2));
    float r1 = fsqrt_ap(fmaf(4.0f, E, 1.0f));        // = 1 + A^2 = w^2
    float A2 = fmaxf(r1 - 1.0f, 1e-12f);             // exact identity
    float rsq = frsqrt_ap(r1);
    float omega  = r1 * rsq;                         // sqrt(r1)
    float m      = fmaf(-0.5f * rsq, rsq, 0.5f);     // (1 - 1/r1)/2 in (0,.5)

    // ---- initial Jacobi triple from (q0, p0) ----
    float invA = frsqrt_ap(A2);
    float A    = A2 * invA;
    float cn0  = fminf(fmaxf(q0 * invA, -1.0f), 1.0f);
    float sn0sq = fmaxf(fmaf(-cn0, cn0, 1.0f), 0.0f);
    float dn0  = fsqrt_ap(fmaf(-m, sn0sq, 1.0f));    // >= sqrt(1-m) > 0.7
    float sn0  = copysignf(fsqrt_ap(sn0sq), -p0);    // p = -A w sn dn

    // ---- Landen moduli: k1 exact, k2/k3 by series ----
    float kp  = fsqrt_ap(1.0f - m);                  // >= 0.707
    float k1  = (1.0f - kp) * frcp_ap(1.0f + kp);    // <= 0.172
    float t   = k1 * k1;                             // <= 0.0295
    float k2  = 0.25f * t * fmaf(t, fmaf(0.34375f, t, 0.5f), 1.0f); // <=7.4e-3
    float k3  = 0.25f * k2 * k2;                     // <= 1.4e-5
    float Pfac = (1.0f + k1) * (1.0f + (k2 + k3));   // 2K/pi

    // ---- forward evaluation at b = 10*omega ----
    float v = 10.0f * omega * frcp_ap(Pfac);         // <= ~50
    const float INV2PI = 0.15915494309189535f;
    const float PI2_HI = 6.28125f;                   // exact in fp32
    const float PI2_LO = 1.9353071795864769e-3f;
    float nn = rintf(v * INV2PI);
    float r  = fmaf(-nn, PI2_HI, v);
    r = fmaf(-nn, PI2_LO, r);
    float sn = __sinf(r), cn = __cosf(r);            // level-2 funcs (dn = 1)

    // ascend k2: 1/(1+x) ~= 1 - x + x^2  (x <= 7.4e-3, err 4e-7)
    float x2   = k2 * sn * sn;
    float rd2  = fmaf(x2, x2, 1.0f) - x2;
    float sn1  = (1.0f + k2) * sn * rd2;
    float cn1  = cn * rd2;
    float dn1  = (1.0f - x2) * rd2;

    // ascend k1: full reciprocal (x up to 0.172)
    float x1   = k1 * sn1 * sn1;
    float rd1  = frcp_ap(1.0f + x1);
    float snb  = (1.0f + k1) * sn1 * rd1;
    float cnb  = cn1 * dn1 * rd1;
    float dnb  = (1.0f - x1) * rd1;

    // ---- addition theorem: u = u0 + b ----
    float D   = frcp_ap(fmaf(-m * sn0sq, snb * snb, 1.0f));
    float snu = (sn0 * cnb * dnb + snb * cn0 * dn0) * D;
    float cnu = fmaf(cn0, cnb, -(sn0 * dn0) * (snb * dnb)) * D;
    float dnu = fmaf(dn0, dnb, -(m * sn0 * snb) * (cn0 * cnb)) * D;

    return make_float2(A * cnu, -A * omega * snu * dnu);
}

__global__ __launch_bounds__(128) void ham_exact_kernel(
    const float4* __restrict__ in, float4* __restrict__ out, int n4)
{
    int i = blockIdx.x * blockDim.x + threadIdx.x;
    if (i >= n4) return;

    float4 v = in[i];                  // two independent (q,p) pairs
    float2 a = duffing_exact(v.x, v.y);
    float2 b = duffing_exact(v.z, v.w);
    out[i] = make_float4(a.x, a.y, b.x, b.y);
}

extern "C" void kernel_launch(void* const* d_in, const int* in_sizes, int n_in,
                              void* d_out, int out_size) {
    const float4* in = (const float4*)d_in[0];
    float4* out = (float4*)d_out;
    int n4 = in_sizes[0] / 4;              // 131072 float4 = 2 pairs each
    int block = 128;
    int grid = (n4 + block - 1) / block;   // 1024 blocks, single wave
    ham_exact_kernel<<<grid, block>>>(in, out, n4);
}